// round 5
// baseline (speedup 1.0000x reference)
#include <cuda_runtime.h>
#include <cuda_fp16.h>

#define NB 32
#define NN 1024
#define NM 1024
#define CSH8 6.104793232414985f   /* ln(448) */

// K'' = 448*exp(-D/eps) stored as e4m3 fp8. 32 MB — comfortably L2-resident.
__device__ unsigned char g_K8[(size_t)NB * NN * NM];
__device__ float g_s[NB * NN];        // row sums  s_i = sum_j K v_j
__device__ float g_t0[NB * NM];       // ping-pong col sums
__device__ float g_t1[NB * NM];

// ---- fp8 helpers -----------------------------------------------------------
__device__ __forceinline__ unsigned short pack_e4m3x2(float lo, float hi) {
    unsigned short r;
    asm("cvt.rn.satfinite.e4m3x2.f32 %0, %1, %2;" : "=h"(r) : "f"(hi), "f"(lo));
    return r;
}
// 4 packed e4m3 (byte0 = elem0) -> float4 (exact via fp16)
__device__ __forceinline__ float4 e4m3x4_to_float4(unsigned int w) {
    unsigned int h0, h1;
    asm("{\n\t.reg .b16 a, b;\n\t"
        "mov.b32 {a, b}, %2;\n\t"
        "cvt.rn.f16x2.e4m3x2 %0, a;\n\t"
        "cvt.rn.f16x2.e4m3x2 %1, b;\n\t}"
        : "=r"(h0), "=r"(h1) : "r"(w));
    __half2 H0 = *reinterpret_cast<__half2*>(&h0);
    __half2 H1 = *reinterpret_cast<__half2*>(&h1);
    float2 f0 = __half22float2(H0);
    float2 f1 = __half22float2(H1);
    return make_float4(f0.x, f0.y, f1.x, f1.y);
}

// ---------------------------------------------------------------------------
// Convert: K8 = e4m3(448*exp(-10D)); t0 = 1 (v0); out = 0.
// grid 16384 x 256, 8 elements per thread.
// ---------------------------------------------------------------------------
__global__ __launch_bounds__(256) void k_convert(const float4* __restrict__ D4,
                                                 float* __restrict__ out) {
    int idx = blockIdx.x * 256 + threadIdx.x;      // 0 .. 4194303
    float4 d0 = D4[2 * idx];
    float4 d1 = D4[2 * idx + 1];
    float e0 = __expf(fmaf(d0.x, -10.0f, CSH8));
    float e1 = __expf(fmaf(d0.y, -10.0f, CSH8));
    float e2 = __expf(fmaf(d0.z, -10.0f, CSH8));
    float e3 = __expf(fmaf(d0.w, -10.0f, CSH8));
    float e4 = __expf(fmaf(d1.x, -10.0f, CSH8));
    float e5 = __expf(fmaf(d1.y, -10.0f, CSH8));
    float e6 = __expf(fmaf(d1.z, -10.0f, CSH8));
    float e7 = __expf(fmaf(d1.w, -10.0f, CSH8));
    unsigned short p0 = pack_e4m3x2(e0, e1);
    unsigned short p1 = pack_e4m3x2(e2, e3);
    unsigned short p2 = pack_e4m3x2(e4, e5);
    unsigned short p3 = pack_e4m3x2(e6, e7);
    uint2 w;
    w.x = (unsigned int)p0 | ((unsigned int)p1 << 16);
    w.y = (unsigned int)p2 | ((unsigned int)p3 << 16);
    reinterpret_cast<uint2*>(g_K8)[idx] = w;

    if (idx < NB * NM) g_t0[idx] = 1.0f;
    if (idx == 0) *out = 0.0f;
}

// ---------------------------------------------------------------------------
// Row pass: s_i = sum_j K_ij * v_j, v_j = 1/tIn_j. Zeroes tOut for the col
// pass (safe: tOut's old contents were last read in the previous row pass).
// grid 4096 x 256; warp per row.
// ---------------------------------------------------------------------------
__global__ __launch_bounds__(256) void k_row(int parity) {
    const float* __restrict__ tIn  = parity ? g_t1 : g_t0;
    float* __restrict__       tOut = parity ? g_t0 : g_t1;
    __shared__ float4 sv[NM / 4];

    int tid   = threadIdx.x;
    int grow0 = blockIdx.x * 8;
    int b     = grow0 >> 10;

    if (tid < 8) tOut[blockIdx.x * 8 + tid] = 0.0f;

    float4 t4 = reinterpret_cast<const float4*>(tIn)[b * (NM / 4) + tid];
    sv[tid] = make_float4(1.0f / t4.x, 1.0f / t4.y, 1.0f / t4.z, 1.0f / t4.w);
    __syncthreads();

    int warp = tid >> 5, lane = tid & 31;
    int row  = grow0 + warp;
    const uint2* __restrict__ Kr =
        reinterpret_cast<const uint2*>(g_K8) + (size_t)row * (NM / 8);

    float acc = 0.0f;
#pragma unroll
    for (int it = 0; it < 4; ++it) {
        int q = lane + it * 32;              // uint2 index: 8 elems
        uint2 p = Kr[q];
        float4 a = e4m3x4_to_float4(p.x);
        float4 c = e4m3x4_to_float4(p.y);
        float4 v0 = sv[2 * q];
        float4 v1 = sv[2 * q + 1];
        acc = fmaf(a.x, v0.x, acc);
        acc = fmaf(a.y, v0.y, acc);
        acc = fmaf(a.z, v0.z, acc);
        acc = fmaf(a.w, v0.w, acc);
        acc = fmaf(c.x, v1.x, acc);
        acc = fmaf(c.y, v1.y, acc);
        acc = fmaf(c.z, v1.z, acc);
        acc = fmaf(c.w, v1.w, acc);
    }
#pragma unroll
    for (int o = 16; o > 0; o >>= 1) acc += __shfl_xor_sync(0xffffffffu, acc, o);
    if (lane == 0) g_s[row] = acc;
}

// ---------------------------------------------------------------------------
// Col pass: tOut_j += sum_i K_ij * u_i over a 32-row chunk, u_i = 1/s_i.
// grid 1024 (32 batches x 32 chunks) x 256; thread owns 4 consecutive cols.
// ---------------------------------------------------------------------------
__global__ __launch_bounds__(256) void k_col(int parity) {
    float* __restrict__ tOut = parity ? g_t0 : g_t1;
    __shared__ float su[32];

    int tid = threadIdx.x;
    int b   = blockIdx.x >> 5;
    int i0  = (blockIdx.x & 31) * 32;

    if (tid < 32) su[tid] = 1.0f / g_s[b * NN + i0 + tid];
    __syncthreads();

    const unsigned int* __restrict__ Kb =
        reinterpret_cast<const unsigned int*>(g_K8 + ((size_t)(b * NN + i0)) * NM) + tid;

    float4 acc = make_float4(0.f, 0.f, 0.f, 0.f);
#pragma unroll 8
    for (int i = 0; i < 32; ++i) {
        float u = su[i];
        float4 f = e4m3x4_to_float4(Kb[(size_t)i * (NM / 4)]);
        acc.x = fmaf(f.x, u, acc.x);
        acc.y = fmaf(f.y, u, acc.y);
        acc.z = fmaf(f.z, u, acc.z);
        acc.w = fmaf(f.w, u, acc.w);
    }
    float* to = tOut + b * NM + tid * 4;
    atomicAdd(to + 0, acc.x);
    atomicAdd(to + 1, acc.y);
    atomicAdd(to + 2, acc.z);
    atomicAdd(to + 3, acc.w);
}

// ---------------------------------------------------------------------------
// Final: loss = (0.1/NB) * sum_ij u_i v_j * f_ij * (ln448 - ln f_ij),
// f = float(K8), D = 0.1*(ln448 - ln f).  The 448 scale is absorbed by u —
// P = u*K''*v is scale-invariant, so NO /448 here (Round-4 bug).
// u = 1/g_s (20th row pass), v = 1/g_t0 (20th col pass).
// grid 4096 x 256; warp per row.
// ---------------------------------------------------------------------------
__global__ __launch_bounds__(256) void k_final(float* __restrict__ out) {
    const float* __restrict__ tIn = g_t0;   // k=19, parity 1 -> tOut = g_t0
    __shared__ float4 sv[NM / 4];
    __shared__ float part[8];

    int tid   = threadIdx.x;
    int grow0 = blockIdx.x * 8;
    int b     = grow0 >> 10;

    float4 t4 = reinterpret_cast<const float4*>(tIn)[b * (NM / 4) + tid];
    sv[tid] = make_float4(1.0f / t4.x, 1.0f / t4.y, 1.0f / t4.z, 1.0f / t4.w);
    __syncthreads();

    int warp = tid >> 5, lane = tid & 31;
    int row  = grow0 + warp;
    const uint2* __restrict__ Kr =
        reinterpret_cast<const uint2*>(g_K8) + (size_t)row * (NM / 8);

    float acc = 0.0f;
#pragma unroll
    for (int it = 0; it < 4; ++it) {
        int q = lane + it * 32;
        uint2 p = Kr[q];
        float4 a = e4m3x4_to_float4(p.x);
        float4 c = e4m3x4_to_float4(p.y);
        float4 v0 = sv[2 * q];
        float4 v1 = sv[2 * q + 1];
        acc = fmaf(a.x * (CSH8 - __logf(a.x)), v0.x, acc);
        acc = fmaf(a.y * (CSH8 - __logf(a.y)), v0.y, acc);
        acc = fmaf(a.z * (CSH8 - __logf(a.z)), v0.z, acc);
        acc = fmaf(a.w * (CSH8 - __logf(a.w)), v0.w, acc);
        acc = fmaf(c.x * (CSH8 - __logf(c.x)), v1.x, acc);
        acc = fmaf(c.y * (CSH8 - __logf(c.y)), v1.y, acc);
        acc = fmaf(c.z * (CSH8 - __logf(c.z)), v1.z, acc);
        acc = fmaf(c.w * (CSH8 - __logf(c.w)), v1.w, acc);
    }
#pragma unroll
    for (int o = 16; o > 0; o >>= 1) acc += __shfl_xor_sync(0xffffffffu, acc, o);
    if (lane == 0) part[warp] = acc / g_s[row];
    __syncthreads();
    if (tid == 0) {
        float s2 = 0.0f;
#pragma unroll
        for (int w = 0; w < 8; ++w) s2 += part[w];
        atomicAdd(out, s2 * (0.1f / (float)NB));
    }
}

// ---------------------------------------------------------------------------
extern "C" void kernel_launch(void* const* d_in, const int* in_sizes, int n_in,
                              void* d_out, int out_size) {
    const float4* D4 = reinterpret_cast<const float4*>(d_in[0]);
    float* out = reinterpret_cast<float*>(d_out);

    k_convert<<<16384, 256>>>(D4, out);
    for (int k = 0; k < 20; ++k) {
        int parity = k & 1;
        k_row<<<4096, 256>>>(parity);
        k_col<<<1024, 256>>>(parity);
    }
    k_final<<<4096, 256>>>(out);
}

// round 6
// speedup vs baseline: 1.1859x; 1.1859x over previous
#include <cuda_runtime.h>
#include <cuda_fp16.h>

#define NB 32
#define NN 1024
#define NM 1024
#define CSH8 6.104793232414985f   /* ln(448) */

// K'' = 448*exp(-D/eps) stored as e4m3 fp8. 32 MB — L2-resident.
__device__ unsigned char g_K8[(size_t)NB * NN * NM];
__device__ float g_s[NB * NN];        // row sums  s_i = sum_j K v_j
__device__ float g_t0[NB * NM];       // ping-pong col sums
__device__ float g_t1[NB * NM];

// ---- fp8 helpers -----------------------------------------------------------
__device__ __forceinline__ unsigned short pack_e4m3x2(float lo, float hi) {
    unsigned short r;
    asm("cvt.rn.satfinite.e4m3x2.f32 %0, %1, %2;" : "=h"(r) : "f"(hi), "f"(lo));
    return r;
}
// 4 packed e4m3 (byte0 = elem0) -> float4 (exact via fp16)
__device__ __forceinline__ float4 e4m3x4_to_float4(unsigned int w) {
    unsigned int h0, h1;
    asm("{\n\t.reg .b16 a, b;\n\t"
        "mov.b32 {a, b}, %2;\n\t"
        "cvt.rn.f16x2.e4m3x2 %0, a;\n\t"
        "cvt.rn.f16x2.e4m3x2 %1, b;\n\t}"
        : "=r"(h0), "=r"(h1) : "r"(w));
    __half2 H0 = *reinterpret_cast<__half2*>(&h0);
    __half2 H1 = *reinterpret_cast<__half2*>(&h1);
    float2 f0 = __half22float2(H0);
    float2 f1 = __half22float2(H1);
    return make_float4(f0.x, f0.y, f1.x, f1.y);
}

// ---------------------------------------------------------------------------
// Convert: K8 = e4m3(448*exp(-10D)); t0 = 1 (v0); out = 0.
// ---------------------------------------------------------------------------
__global__ __launch_bounds__(256) void k_convert(const float4* __restrict__ D4,
                                                 float* __restrict__ out) {
    int idx = blockIdx.x * 256 + threadIdx.x;      // 0 .. 4194303
    float4 d0 = D4[2 * idx];
    float4 d1 = D4[2 * idx + 1];
    float e0 = __expf(fmaf(d0.x, -10.0f, CSH8));
    float e1 = __expf(fmaf(d0.y, -10.0f, CSH8));
    float e2 = __expf(fmaf(d0.z, -10.0f, CSH8));
    float e3 = __expf(fmaf(d0.w, -10.0f, CSH8));
    float e4 = __expf(fmaf(d1.x, -10.0f, CSH8));
    float e5 = __expf(fmaf(d1.y, -10.0f, CSH8));
    float e6 = __expf(fmaf(d1.z, -10.0f, CSH8));
    float e7 = __expf(fmaf(d1.w, -10.0f, CSH8));
    unsigned short p0 = pack_e4m3x2(e0, e1);
    unsigned short p1 = pack_e4m3x2(e2, e3);
    unsigned short p2 = pack_e4m3x2(e4, e5);
    unsigned short p3 = pack_e4m3x2(e6, e7);
    uint2 w;
    w.x = (unsigned int)p0 | ((unsigned int)p1 << 16);
    w.y = (unsigned int)p2 | ((unsigned int)p3 << 16);
    reinterpret_cast<uint2*>(g_K8)[idx] = w;

    if (idx < NB * NM) g_t0[idx] = 1.0f;
    if (idx == 0) *out = 0.0f;
}

// ---------------------------------------------------------------------------
// Row pass: s_i = sum_j K_ij / tIn_j.  grid 512 x 256; block = 64 rows,
// warp = 8 rows.  v-slice held in registers per column-phase (low LDS).
// Zeroes tOut for the following col pass (safe per ping-pong schedule).
// ---------------------------------------------------------------------------
__global__ __launch_bounds__(256) void k_row(int parity) {
    const float* __restrict__ tIn  = parity ? g_t1 : g_t0;
    float* __restrict__       tOut = parity ? g_t0 : g_t1;
    __shared__ float4 sv[NM / 4];

    int tid  = threadIdx.x;
    int w    = tid >> 5, lane = tid & 31;
    int b    = blockIdx.x >> 4;             // 16 blocks per batch
    int row0 = blockIdx.x * 64 + w * 8;

    if (tid < 64) tOut[blockIdx.x * 64 + tid] = 0.0f;   // 512*64 = 32768 ✓

    float4 t4 = reinterpret_cast<const float4*>(tIn)[b * (NM / 4) + tid];
    sv[tid] = make_float4(__fdividef(1.0f, t4.x), __fdividef(1.0f, t4.y),
                          __fdividef(1.0f, t4.z), __fdividef(1.0f, t4.w));
    __syncthreads();

    const uint2* __restrict__ Kr =
        reinterpret_cast<const uint2*>(g_K8) + (size_t)row0 * (NM / 8);

    float acc[8];
#pragma unroll
    for (int r = 0; r < 8; ++r) acc[r] = 0.0f;

#pragma unroll
    for (int it = 0; it < 4; ++it) {
        int q = it * 32 + lane;             // uint2 index within a row
        float4 v0 = sv[2 * q];
        float4 v1 = sv[2 * q + 1];
#pragma unroll
        for (int r = 0; r < 8; ++r) {
            uint2 p = Kr[(size_t)r * (NM / 8) + q];
            float4 a = e4m3x4_to_float4(p.x);
            float4 c = e4m3x4_to_float4(p.y);
            float s = acc[r];
            s = fmaf(a.x, v0.x, s);
            s = fmaf(a.y, v0.y, s);
            s = fmaf(a.z, v0.z, s);
            s = fmaf(a.w, v0.w, s);
            s = fmaf(c.x, v1.x, s);
            s = fmaf(c.y, v1.y, s);
            s = fmaf(c.z, v1.z, s);
            s = fmaf(c.w, v1.w, s);
            acc[r] = s;
        }
    }

    // 8 independent shuffle trees (ILP hides the 5-level latency).
#pragma unroll
    for (int r = 0; r < 8; ++r) {
        float s = acc[r];
#pragma unroll
        for (int o = 16; o > 0; o >>= 1) s += __shfl_xor_sync(0xffffffffu, s, o);
        if (lane == 0) g_s[row0 + r] = s;
    }
}

// ---------------------------------------------------------------------------
// Col pass: tOut_j += sum_i K_ij * u_i over a 64-row chunk, u_i = 1/s_i.
// grid 512 (32 batches x 16 chunks) x 128; thread owns 8 consecutive cols,
// register accumulators, no shuffles, 8 REDG tail.
// ---------------------------------------------------------------------------
__global__ __launch_bounds__(128) void k_col(int parity) {
    float* __restrict__ tOut = parity ? g_t0 : g_t1;
    __shared__ float su[64];

    int tid = threadIdx.x;
    int b   = blockIdx.x >> 4;
    int i0  = (blockIdx.x & 15) * 64;

    if (tid < 64) su[tid] = __fdividef(1.0f, g_s[b * NN + i0 + tid]);
    __syncthreads();

    const uint2* __restrict__ Kb =
        reinterpret_cast<const uint2*>(g_K8) + (size_t)(b * NN + i0) * (NM / 8) + tid;

    float a0 = 0.f, a1 = 0.f, a2 = 0.f, a3 = 0.f;
    float a4 = 0.f, a5 = 0.f, a6 = 0.f, a7 = 0.f;
#pragma unroll 8
    for (int i = 0; i < 64; ++i) {
        float u = su[i];
        uint2 p = Kb[(size_t)i * (NM / 8)];
        float4 x = e4m3x4_to_float4(p.x);
        float4 y = e4m3x4_to_float4(p.y);
        a0 = fmaf(x.x, u, a0);
        a1 = fmaf(x.y, u, a1);
        a2 = fmaf(x.z, u, a2);
        a3 = fmaf(x.w, u, a3);
        a4 = fmaf(y.x, u, a4);
        a5 = fmaf(y.y, u, a5);
        a6 = fmaf(y.z, u, a6);
        a7 = fmaf(y.w, u, a7);
    }
    float* to = tOut + b * NM + tid * 8;
    atomicAdd(to + 0, a0);
    atomicAdd(to + 1, a1);
    atomicAdd(to + 2, a2);
    atomicAdd(to + 3, a3);
    atomicAdd(to + 4, a4);
    atomicAdd(to + 5, a5);
    atomicAdd(to + 6, a6);
    atomicAdd(to + 7, a7);
}

// ---------------------------------------------------------------------------
// Final: loss = (0.1/NB) * sum_ij u_i v_j * f_ij * (ln448 - ln f_ij),
// f = float(K8); the 448 scale is absorbed by u (scale invariance).
// u = 1/g_s (20th row pass), v = 1/g_t0 (20th col pass).
// ---------------------------------------------------------------------------
__global__ __launch_bounds__(256) void k_final(float* __restrict__ out) {
    const float* __restrict__ tIn = g_t0;   // k=19, parity 1 -> tOut = g_t0
    __shared__ float4 sv[NM / 4];
    __shared__ float part[8];

    int tid   = threadIdx.x;
    int grow0 = blockIdx.x * 8;
    int b     = grow0 >> 10;

    float4 t4 = reinterpret_cast<const float4*>(tIn)[b * (NM / 4) + tid];
    sv[tid] = make_float4(__fdividef(1.0f, t4.x), __fdividef(1.0f, t4.y),
                          __fdividef(1.0f, t4.z), __fdividef(1.0f, t4.w));
    __syncthreads();

    int warp = tid >> 5, lane = tid & 31;
    int row  = grow0 + warp;
    const uint2* __restrict__ Kr =
        reinterpret_cast<const uint2*>(g_K8) + (size_t)row * (NM / 8);

    float acc = 0.0f;
#pragma unroll
    for (int it = 0; it < 4; ++it) {
        int q = lane + it * 32;
        uint2 p = Kr[q];
        float4 a = e4m3x4_to_float4(p.x);
        float4 c = e4m3x4_to_float4(p.y);
        float4 v0 = sv[2 * q];
        float4 v1 = sv[2 * q + 1];
        acc = fmaf(a.x * (CSH8 - __logf(a.x)), v0.x, acc);
        acc = fmaf(a.y * (CSH8 - __logf(a.y)), v0.y, acc);
        acc = fmaf(a.z * (CSH8 - __logf(a.z)), v0.z, acc);
        acc = fmaf(a.w * (CSH8 - __logf(a.w)), v0.w, acc);
        acc = fmaf(c.x * (CSH8 - __logf(c.x)), v1.x, acc);
        acc = fmaf(c.y * (CSH8 - __logf(c.y)), v1.y, acc);
        acc = fmaf(c.z * (CSH8 - __logf(c.z)), v1.z, acc);
        acc = fmaf(c.w * (CSH8 - __logf(c.w)), v1.w, acc);
    }
#pragma unroll
    for (int o = 16; o > 0; o >>= 1) acc += __shfl_xor_sync(0xffffffffu, acc, o);
    if (lane == 0) part[warp] = acc / g_s[row];
    __syncthreads();
    if (tid == 0) {
        float s2 = 0.0f;
#pragma unroll
        for (int w = 0; w < 8; ++w) s2 += part[w];
        atomicAdd(out, s2 * (0.1f / (float)NB));
    }
}

// ---------------------------------------------------------------------------
extern "C" void kernel_launch(void* const* d_in, const int* in_sizes, int n_in,
                              void* d_out, int out_size) {
    const float4* D4 = reinterpret_cast<const float4*>(d_in[0]);
    float* out = reinterpret_cast<float*>(d_out);

    k_convert<<<16384, 256>>>(D4, out);
    for (int k = 0; k < 20; ++k) {
        int parity = k & 1;
        k_row<<<512, 256>>>(parity);
        k_col<<<512, 128>>>(parity);
    }
    k_final<<<4096, 256>>>(out);
}

// round 7
// speedup vs baseline: 1.3351x; 1.1258x over previous
#include <cuda_runtime.h>
#include <cuda_fp16.h>

#define NB 32
#define NN 1024
#define NM 1024
#define CSH8 6.104793232414985f   /* ln(448) */

// K'' = 448*exp(-D/eps) stored as e4m3 fp8. 32 MB — L2-resident.
__device__ unsigned char g_K8[(size_t)NB * NN * NM];
__device__ float g_s[NB * NN];        // row sums  s_i = sum_j K v_j
__device__ float g_t0[NB * NM];       // ping-pong col sums
__device__ float g_t1[NB * NM];

// ---- fp8 helpers -----------------------------------------------------------
__device__ __forceinline__ unsigned short pack_e4m3x2(float lo, float hi) {
    unsigned short r;
    asm("cvt.rn.satfinite.e4m3x2.f32 %0, %1, %2;" : "=h"(r) : "f"(hi), "f"(lo));
    return r;
}
// 4 packed e4m3 (byte0 = elem0) -> float4 (exact via fp16)
__device__ __forceinline__ float4 e4m3x4_to_float4(unsigned int w) {
    unsigned int h0, h1;
    asm("{\n\t.reg .b16 a, b;\n\t"
        "mov.b32 {a, b}, %2;\n\t"
        "cvt.rn.f16x2.e4m3x2 %0, a;\n\t"
        "cvt.rn.f16x2.e4m3x2 %1, b;\n\t}"
        : "=r"(h0), "=r"(h1) : "r"(w));
    __half2 H0 = *reinterpret_cast<__half2*>(&h0);
    __half2 H1 = *reinterpret_cast<__half2*>(&h1);
    float2 f0 = __half22float2(H0);
    float2 f1 = __half22float2(H1);
    return make_float4(f0.x, f0.y, f1.x, f1.y);
}

// dot of 16 fp8 elems (uint4) with 4 float4 v regs, accumulated into s
__device__ __forceinline__ float dot16(uint4 p, const float4& v0, const float4& v1,
                                       const float4& v2, const float4& v3, float s) {
    float4 a = e4m3x4_to_float4(p.x);
    float4 b = e4m3x4_to_float4(p.y);
    float4 c = e4m3x4_to_float4(p.z);
    float4 d = e4m3x4_to_float4(p.w);
    s = fmaf(a.x, v0.x, s); s = fmaf(a.y, v0.y, s);
    s = fmaf(a.z, v0.z, s); s = fmaf(a.w, v0.w, s);
    s = fmaf(b.x, v1.x, s); s = fmaf(b.y, v1.y, s);
    s = fmaf(b.z, v1.z, s); s = fmaf(b.w, v1.w, s);
    s = fmaf(c.x, v2.x, s); s = fmaf(c.y, v2.y, s);
    s = fmaf(c.z, v2.z, s); s = fmaf(c.w, v2.w, s);
    s = fmaf(d.x, v3.x, s); s = fmaf(d.y, v3.y, s);
    s = fmaf(d.z, v3.z, s); s = fmaf(d.w, v3.w, s);
    return s;
}

// ---------------------------------------------------------------------------
// Convert: K8 = e4m3(448*exp(-10D)); t0 = 1 (v0); out = 0.
// ---------------------------------------------------------------------------
__global__ __launch_bounds__(256) void k_convert(const float4* __restrict__ D4,
                                                 float* __restrict__ out) {
    int idx = blockIdx.x * 256 + threadIdx.x;      // 0 .. 4194303
    float4 d0 = D4[2 * idx];
    float4 d1 = D4[2 * idx + 1];
    float e0 = __expf(fmaf(d0.x, -10.0f, CSH8));
    float e1 = __expf(fmaf(d0.y, -10.0f, CSH8));
    float e2 = __expf(fmaf(d0.z, -10.0f, CSH8));
    float e3 = __expf(fmaf(d0.w, -10.0f, CSH8));
    float e4 = __expf(fmaf(d1.x, -10.0f, CSH8));
    float e5 = __expf(fmaf(d1.y, -10.0f, CSH8));
    float e6 = __expf(fmaf(d1.z, -10.0f, CSH8));
    float e7 = __expf(fmaf(d1.w, -10.0f, CSH8));
    unsigned short p0 = pack_e4m3x2(e0, e1);
    unsigned short p1 = pack_e4m3x2(e2, e3);
    unsigned short p2 = pack_e4m3x2(e4, e5);
    unsigned short p3 = pack_e4m3x2(e6, e7);
    uint2 w;
    w.x = (unsigned int)p0 | ((unsigned int)p1 << 16);
    w.y = (unsigned int)p2 | ((unsigned int)p3 << 16);
    reinterpret_cast<uint2*>(g_K8)[idx] = w;

    if (idx < NB * NM) g_t0[idx] = 1.0f;
    if (idx == 0) *out = 0.0f;
}

// ---------------------------------------------------------------------------
// Row pass: s_i = sum_j K_ij / tIn_j.  grid 1024 x 256; block = 32 rows,
// warp = 4 rows.  LDG.128, v slice in registers per phase (2 phases).
// Zeroes tOut for the following col pass (safe per ping-pong schedule).
// ---------------------------------------------------------------------------
__global__ __launch_bounds__(256) void k_row(int parity) {
    const float* __restrict__ tIn  = parity ? g_t1 : g_t0;
    float* __restrict__       tOut = parity ? g_t0 : g_t1;
    __shared__ float4 sv[NM / 4];

    int tid  = threadIdx.x;
    int w    = tid >> 5, lane = tid & 31;
    int b    = blockIdx.x >> 5;              // 32 blocks per batch
    int row0 = blockIdx.x * 32 + w * 4;

    if (tid < 32) tOut[blockIdx.x * 32 + tid] = 0.0f;   // 1024*32 = 32768 ✓

    float4 t4 = reinterpret_cast<const float4*>(tIn)[b * (NM / 4) + tid];
    sv[tid] = make_float4(__fdividef(1.0f, t4.x), __fdividef(1.0f, t4.y),
                          __fdividef(1.0f, t4.z), __fdividef(1.0f, t4.w));
    __syncthreads();

    const uint4* __restrict__ Kr =
        reinterpret_cast<const uint4*>(g_K8) + (size_t)row0 * (NM / 16);

    float acc[4] = {0.f, 0.f, 0.f, 0.f};

#pragma unroll
    for (int ph = 0; ph < 2; ++ph) {
        int q = ph * 32 + lane;              // uint4 index within a row (0..63)
        float4 v0 = sv[4 * q + 0];
        float4 v1 = sv[4 * q + 1];
        float4 v2 = sv[4 * q + 2];
        float4 v3 = sv[4 * q + 3];
        uint4 p0 = Kr[0 * (NM / 16) + q];
        uint4 p1 = Kr[1 * (NM / 16) + q];
        uint4 p2 = Kr[2 * (NM / 16) + q];
        uint4 p3 = Kr[3 * (NM / 16) + q];
        acc[0] = dot16(p0, v0, v1, v2, v3, acc[0]);
        acc[1] = dot16(p1, v0, v1, v2, v3, acc[1]);
        acc[2] = dot16(p2, v0, v1, v2, v3, acc[2]);
        acc[3] = dot16(p3, v0, v1, v2, v3, acc[3]);
    }

    // 4 independent shuffle trees (ILP hides the 5-level latency).
#pragma unroll
    for (int r = 0; r < 4; ++r) {
        float s = acc[r];
#pragma unroll
        for (int o = 16; o > 0; o >>= 1) s += __shfl_xor_sync(0xffffffffu, s, o);
        if (lane == 0) g_s[row0 + r] = s;
    }
}

// ---------------------------------------------------------------------------
// Col pass: tOut_j += sum_i K_ij * u_i over a 64-row chunk, u_i = 1/s_i.
// grid 512 (32 batches x 16 chunks) x 256. Block = 4 sub-groups of 64 threads;
// sub-group g handles 16 rows, thread owns 16 consecutive cols (LDG.128,
// fully unrolled = 16 loads in flight). smem merge, then 4 REDG per thread.
// ---------------------------------------------------------------------------
__global__ __launch_bounds__(256) void k_col(int parity) {
    float* __restrict__ tOut = parity ? g_t0 : g_t1;
    __shared__ float su[64];
    __shared__ float stage[4][NM];       // 16 KB

    int tid = threadIdx.x;
    int cg  = tid >> 6;                  // row sub-chunk 0..3
    int ct  = tid & 63;                  // col thread: cols [ct*16, ct*16+16)
    int b   = blockIdx.x >> 4;
    int i0  = (blockIdx.x & 15) * 64;

    if (tid < 64) su[tid] = __fdividef(1.0f, g_s[b * NN + i0 + tid]);
    __syncthreads();

    const uint4* __restrict__ Kb =
        reinterpret_cast<const uint4*>(g_K8)
        + (size_t)(b * NN + i0 + cg * 16) * (NM / 16) + ct;

    float4 A = {0,0,0,0}, B = {0,0,0,0}, C = {0,0,0,0}, E = {0,0,0,0};
#pragma unroll
    for (int i = 0; i < 16; ++i) {
        float u = su[cg * 16 + i];
        uint4 p = Kb[(size_t)i * (NM / 16)];
        float4 x = e4m3x4_to_float4(p.x);
        float4 y = e4m3x4_to_float4(p.y);
        float4 z = e4m3x4_to_float4(p.z);
        float4 t = e4m3x4_to_float4(p.w);
        A.x = fmaf(x.x, u, A.x); A.y = fmaf(x.y, u, A.y);
        A.z = fmaf(x.z, u, A.z); A.w = fmaf(x.w, u, A.w);
        B.x = fmaf(y.x, u, B.x); B.y = fmaf(y.y, u, B.y);
        B.z = fmaf(y.z, u, B.z); B.w = fmaf(y.w, u, B.w);
        C.x = fmaf(z.x, u, C.x); C.y = fmaf(z.y, u, C.y);
        C.z = fmaf(z.z, u, C.z); C.w = fmaf(z.w, u, C.w);
        E.x = fmaf(t.x, u, E.x); E.y = fmaf(t.y, u, E.y);
        E.z = fmaf(t.z, u, E.z); E.w = fmaf(t.w, u, E.w);
    }

    float4* st = reinterpret_cast<float4*>(&stage[cg][ct * 16]);
    st[0] = A; st[1] = B; st[2] = C; st[3] = E;
    __syncthreads();

    // merge 4 sub-chunk partials: thread owns cols [tid*4, tid*4+4)
    const float4* s0 = reinterpret_cast<const float4*>(stage[0]);
    const float4* s1 = reinterpret_cast<const float4*>(stage[1]);
    const float4* s2 = reinterpret_cast<const float4*>(stage[2]);
    const float4* s3 = reinterpret_cast<const float4*>(stage[3]);
    float4 r0 = s0[tid], r1 = s1[tid], r2 = s2[tid], r3 = s3[tid];
    float4 r;
    r.x = (r0.x + r1.x) + (r2.x + r3.x);
    r.y = (r0.y + r1.y) + (r2.y + r3.y);
    r.z = (r0.z + r1.z) + (r2.z + r3.z);
    r.w = (r0.w + r1.w) + (r2.w + r3.w);

    float* to = tOut + b * NM + tid * 4;
    atomicAdd(to + 0, r.x);
    atomicAdd(to + 1, r.y);
    atomicAdd(to + 2, r.z);
    atomicAdd(to + 3, r.w);
}

// ---------------------------------------------------------------------------
// Final: loss = (0.1/NB) * sum_ij u_i v_j * f_ij * (ln448 - ln f_ij),
// f = float(K8); the 448 scale is absorbed by u (scale invariance).
// u = 1/g_s (20th row pass), v = 1/g_t0 (20th col pass).
// ---------------------------------------------------------------------------
__global__ __launch_bounds__(256) void k_final(float* __restrict__ out) {
    const float* __restrict__ tIn = g_t0;   // k=19, parity 1 -> tOut = g_t0
    __shared__ float4 sv[NM / 4];
    __shared__ float part[8];

    int tid   = threadIdx.x;
    int grow0 = blockIdx.x * 8;
    int b     = grow0 >> 10;

    float4 t4 = reinterpret_cast<const float4*>(tIn)[b * (NM / 4) + tid];
    sv[tid] = make_float4(__fdividef(1.0f, t4.x), __fdividef(1.0f, t4.y),
                          __fdividef(1.0f, t4.z), __fdividef(1.0f, t4.w));
    __syncthreads();

    int warp = tid >> 5, lane = tid & 31;
    int row  = grow0 + warp;
    const uint2* __restrict__ Kr =
        reinterpret_cast<const uint2*>(g_K8) + (size_t)row * (NM / 8);

    float acc = 0.0f;
#pragma unroll
    for (int it = 0; it < 4; ++it) {
        int q = lane + it * 32;
        uint2 p = Kr[q];
        float4 a = e4m3x4_to_float4(p.x);
        float4 c = e4m3x4_to_float4(p.y);
        float4 v0 = sv[2 * q];
        float4 v1 = sv[2 * q + 1];
        acc = fmaf(a.x * (CSH8 - __logf(a.x)), v0.x, acc);
        acc = fmaf(a.y * (CSH8 - __logf(a.y)), v0.y, acc);
        acc = fmaf(a.z * (CSH8 - __logf(a.z)), v0.z, acc);
        acc = fmaf(a.w * (CSH8 - __logf(a.w)), v0.w, acc);
        acc = fmaf(c.x * (CSH8 - __logf(c.x)), v1.x, acc);
        acc = fmaf(c.y * (CSH8 - __logf(c.y)), v1.y, acc);
        acc = fmaf(c.z * (CSH8 - __logf(c.z)), v1.z, acc);
        acc = fmaf(c.w * (CSH8 - __logf(c.w)), v1.w, acc);
    }
#pragma unroll
    for (int o = 16; o > 0; o >>= 1) acc += __shfl_xor_sync(0xffffffffu, acc, o);
    if (lane == 0) part[warp] = acc / g_s[row];
    __syncthreads();
    if (tid == 0) {
        float s2 = 0.0f;
#pragma unroll
        for (int w = 0; w < 8; ++w) s2 += part[w];
        atomicAdd(out, s2 * (0.1f / (float)NB));
    }
}

// ---------------------------------------------------------------------------
extern "C" void kernel_launch(void* const* d_in, const int* in_sizes, int n_in,
                              void* d_out, int out_size) {
    const float4* D4 = reinterpret_cast<const float4*>(d_in[0]);
    float* out = reinterpret_cast<float*>(d_out);

    k_convert<<<16384, 256>>>(D4, out);
    for (int k = 0; k < 20; ++k) {
        int parity = k & 1;
        k_row<<<1024, 256>>>(parity);
        k_col<<<512, 256>>>(parity);
    }
    k_final<<<4096, 256>>>(out);
}